// round 13
// baseline (speedup 1.0000x reference)
#include <cuda_runtime.h>
#include <math.h>
#include <stdint.h>

// R13: split-TF32 mma.sync (m16n8k8 HMMA fallback on sm_100).
// out[ch][pt] = sum_b bas[pt][b]*coef[ch][b]  ->  D = A(pt,k) x B(k,ch).
// 3-product split (hh, hl, lh) for ~1e-6 rel err. CTA: 64 pts x 128 ch
// (channel half), 4 warps; warp = 16 pts x 128 ch = 16 ntiles m16n8.
// B smem packed {hi(k),hi(k+4),lo(k),lo(k+4)} -> 1 LDS.128 per 3 HMMA.

#define NPTS    110592
#define NB      30
#define KP      32
#define NOI     256
#define THREADS 128

// dynamic smem offsets
#define A_HI   0                      // 64 x 33 f32 = 8448 (padded rows)
#define A_LO   8448
#define B_PK   16896                  // 128 ch x 272 B = 34816
#define SM_TOT (B_PK + 128 * 272)     // 51712

struct WParams { float w[NB]; };

__device__ __forceinline__ uint32_t f2tf32(float v) {
    uint32_t h; asm("cvt.rna.tf32.f32 %0, %1;" : "=r"(h) : "f"(v)); return h;
}

#define MMA_TF32(ac, a, b0, b1) \
    asm volatile("mma.sync.aligned.m16n8k8.row.col.f32.tf32.tf32.f32 " \
                 "{%0,%1,%2,%3}, {%4,%5,%6,%7}, {%8,%9}, {%0,%1,%2,%3};" \
                 : "+f"((ac)[0]), "+f"((ac)[1]), "+f"((ac)[2]), "+f"((ac)[3]) \
                 : "r"((a)[0]), "r"((a)[1]), "r"((a)[2]), "r"((a)[3]), \
                   "r"(b0), "r"(b1))

__device__ __forceinline__ void basis_eval(float r, float th, float ph,
                                           const float* __restrict__ w,
                                           float* __restrict__ bas)
{
    const float ct  = cosf(th);
    const float st2 = fmaxf(1.0f - ct * ct, 0.0f);
    const float st  = sqrtf(st2);
    const float cp  = cosf(ph);
    const float sp  = sinf(ph);
    const float c2p = cp * cp - sp * sp;
    const float s2p = 2.0f * sp * cp;
    const float c3p = c2p * cp - s2p * sp;
    const float s3p = s2p * cp + c2p * sp;

    const float er1 = expf(-r);
    const float er2 = expf(-0.5f * r);
    const float er3 = expf(-0.33333333333333333f * r);
    const float er4 = expf(-0.25f * r);
    const float rho3 = 0.66666666666666666f * r;
    const float rho4 = 0.5f * r;

    const float F10 = er1;
    const float F20 = er2 * (2.0f - r);
    const float F21 = er2 * r;
    const float F30 = er3 * (3.0f + rho3 * (-3.0f + 0.5f * rho3));
    const float F31 = er3 * rho3 * (4.0f - rho3);
    const float F32 = er3 * rho3 * rho3;
    const float F40 = er4 * (4.0f + rho4 * (-6.0f + rho4 * (2.0f - 0.16666666666666666f * rho4)));
    const float F41 = er4 * rho4 * (10.0f + rho4 * (-5.0f + 0.5f * rho4));
    const float F42 = er4 * rho4 * rho4 * (6.0f - rho4);
    const float F43 = er4 * rho4 * rho4 * rho4;

    const float p10 = ct;
    const float p11 = -st;
    const float p20 = 1.5f * ct * ct - 0.5f;
    const float p21 = -3.0f * ct * st;
    const float p22 = 3.0f * st2;
    const float p30 = (2.5f * ct * ct - 1.5f) * ct;
    const float p31 = (1.5f - 7.5f * ct * ct) * st;
    const float p32 = 15.0f * ct * st2;
    const float p33 = -15.0f * st * st2;

    bas[0]  = w[0]  * F10;
    bas[1]  = w[1]  * F20;
    bas[2]  = w[2]  * F21 * p11 * sp;
    bas[3]  = w[3]  * F21 * p10;
    bas[4]  = w[4]  * F21 * p11 * cp;
    bas[5]  = w[5]  * F30;
    bas[6]  = w[6]  * F31 * p11 * sp;
    bas[7]  = w[7]  * F31 * p10;
    bas[8]  = w[8]  * F31 * p11 * cp;
    bas[9]  = w[9]  * F32 * p22 * s2p;
    bas[10] = w[10] * F32 * p21 * sp;
    bas[11] = w[11] * F32 * p20;
    bas[12] = w[12] * F32 * p21 * cp;
    bas[13] = w[13] * F32 * p22 * c2p;
    bas[14] = w[14] * F40;
    bas[15] = w[15] * F41 * p11 * sp;
    bas[16] = w[16] * F41 * p10;
    bas[17] = w[17] * F41 * p11 * cp;
    bas[18] = w[18] * F42 * p22 * s2p;
    bas[19] = w[19] * F42 * p21 * sp;
    bas[20] = w[20] * F42 * p20;
    bas[21] = w[21] * F42 * p21 * cp;
    bas[22] = w[22] * F42 * p22 * c2p;
    bas[23] = w[23] * F43 * p33 * s3p;
    bas[24] = w[24] * F43 * p32 * s2p;
    bas[25] = w[25] * F43 * p31 * sp;
    bas[26] = w[26] * F43 * p30;
    bas[27] = w[27] * F43 * p31 * cp;
    bas[28] = w[28] * F43 * p32 * c2p;
    bas[29] = w[29] * F43 * p33 * c3p;
}

__global__ __launch_bounds__(THREADS, 3)
void dcconv_hmma(const float* __restrict__ pos,
                 const float* __restrict__ coef,
                 float* __restrict__ out,
                 WParams W)
{
    extern __shared__ char sm[];
    float* Ahi = (float*)(sm + A_HI);               // [64][33]
    float* Alo = (float*)(sm + A_LO);               // [64][33]
    char*  Bpk = sm + B_PK;                         // [128 ch][272 B]

    const int tid   = threadIdx.x;
    const int lane  = tid & 31;
    const int wid   = tid >> 5;
    const int half  = blockIdx.x & 1;
    const int ptile = blockIdx.x >> 1;
    const int ch0   = half * 128;
    const int p0    = ptile * 64;

    // ---- stage: threads 0-63 basis (1 pt each); 64-127 coef (2 ch each) ----
    if (tid < 64) {
        const int p = p0 + tid;
        float bas[KP];
        basis_eval(pos[3 * p + 0], pos[3 * p + 1], pos[3 * p + 2], W.w, bas);
        bas[30] = 0.0f; bas[31] = 0.0f;
#pragma unroll
        for (int k = 0; k < KP; ++k) {
            const float v  = bas[k];
            const uint32_t h = f2tf32(v);
            const float lo = v - __uint_as_float(h);
            Ahi[tid * 33 + k] = __uint_as_float(h);
            Alo[tid * 33 + k] = __uint_as_float(f2tf32(lo));
        }
    } else {
        for (int cc = (tid - 64) * 2; cc < (tid - 64) * 2 + 2; ++cc) {
            const float* crow = coef + (size_t)(ch0 + cc) * NB;
#pragma unroll
            for (int ks = 0; ks < 4; ++ks) {
#pragma unroll
                for (int pq = 0; pq < 4; ++pq) {
                    const int k = ks * 8 + pq;
                    const float v0 = (k     < NB) ? crow[k]     : 0.0f;
                    const float v4 = (k + 4 < NB) ? crow[k + 4] : 0.0f;
                    const uint32_t h0 = f2tf32(v0);
                    const uint32_t h4 = f2tf32(v4);
                    const uint32_t l0 = f2tf32(v0 - __uint_as_float(h0));
                    const uint32_t l4 = f2tf32(v4 - __uint_as_float(h4));
                    *(uint4*)(Bpk + cc * 272 + ks * 64 + pq * 16) =
                        make_uint4(h0, h4, l0, l4);
                }
            }
        }
    }
    __syncthreads();

    // ---- A fragments (per warp, 16 pts starting at wid*16) ----
    const int r = lane >> 2;          // 0..7
    const int q = lane & 3;           // 0..3
    uint32_t ah[4][4], al[4][4];
    {
        const int row0 = wid * 16 + r;
#pragma unroll
        for (int ks = 0; ks < 4; ++ks) {
            const int kb = ks * 8 + q;
            ah[ks][0] = __float_as_uint(Ahi[row0 * 33 + kb]);
            ah[ks][1] = __float_as_uint(Ahi[(row0 + 8) * 33 + kb]);
            ah[ks][2] = __float_as_uint(Ahi[row0 * 33 + kb + 4]);
            ah[ks][3] = __float_as_uint(Ahi[(row0 + 8) * 33 + kb + 4]);
            al[ks][0] = __float_as_uint(Alo[row0 * 33 + kb]);
            al[ks][1] = __float_as_uint(Alo[(row0 + 8) * 33 + kb]);
            al[ks][2] = __float_as_uint(Alo[row0 * 33 + kb + 4]);
            al[ks][3] = __float_as_uint(Alo[(row0 + 8) * 33 + kb + 4]);
        }
    }

    // ---- mainloop: 16 ntiles x 4 ksteps x 3 HMMA ----
    float acc[16][4];
#pragma unroll
    for (int nt = 0; nt < 16; ++nt) {
        acc[nt][0] = 0.0f; acc[nt][1] = 0.0f;
        acc[nt][2] = 0.0f; acc[nt][3] = 0.0f;
    }
    const char* bbase = Bpk + (lane >> 2) * 272 + (lane & 3) * 16;
#pragma unroll
    for (int nt = 0; nt < 16; ++nt) {
#pragma unroll
        for (int ks = 0; ks < 4; ++ks) {
            const uint4 bb = *(const uint4*)(bbase + nt * 2176 + ks * 64);
            MMA_TF32(acc[nt], ah[ks], bb.x, bb.y);   // hi x hi
            MMA_TF32(acc[nt], ah[ks], bb.z, bb.w);   // hi x lo
            MMA_TF32(acc[nt], al[ks], bb.x, bb.y);   // lo x hi
        }
    }

    // ---- epilogue: direct frag stores (4x32B sectors per warp-STG) ----
    const int ptA = p0 + wid * 16 + r;
#pragma unroll
    for (int nt = 0; nt < 16; ++nt) {
        const size_t chA = (size_t)(ch0 + nt * 8 + 2 * q);
        out[chA * NPTS + ptA]           = acc[nt][0];
        out[(chA + 1) * NPTS + ptA]     = acc[nt][1];
        out[chA * NPTS + ptA + 8]       = acc[nt][2];
        out[(chA + 1) * NPTS + ptA + 8] = acc[nt][3];
    }
}

extern "C" void kernel_launch(void* const* d_in, const int* in_sizes, int n_in,
                              void* d_out, int out_size)
{
    const float* pos  = (const float*)d_in[0];
    const float* coef = (const float*)d_in[1];
    if (n_in >= 2 && in_sizes[0] == NOI * NB) {
        coef = (const float*)d_in[0];
        pos  = (const float*)d_in[1];
    }

    const double PI  = 3.14159265358979323846;
    const double K00 = sqrt(1.0 / (4.0 * PI));
    const double K10 = sqrt(3.0 / (4.0 * PI));
    const double K20 = sqrt(5.0 / (4.0 * PI));
    const double K30 = sqrt(7.0 / (4.0 * PI));
    const double A11 = sqrt(3.0 / (4.0 * PI));
    const double A21 = sqrt(5.0 / (12.0 * PI));
    const double A22 = sqrt(5.0 / (48.0 * PI));
    const double A31 = sqrt(7.0 / (24.0 * PI));
    const double A32 = sqrt(7.0 / (240.0 * PI));
    const double A33 = sqrt(7.0 / (1440.0 * PI));

    const double C10 = 2.0;
    const double C20 = sqrt(1.0 / 8.0);
    const double C21 = sqrt(1.0 / 24.0);
    const double C30 = sqrt(16.0 / 972.0);
    const double C31 = sqrt(8.0 / 3888.0);
    const double C32 = sqrt(8.0 / 19440.0);
    const double C40 = sqrt(6.0 / 1536.0);
    const double C41 = sqrt(2.0 / 7680.0);
    const double C42 = sqrt(1.0 / 46080.0);
    const double C43 = sqrt(1.0 / 322560.0);

    WParams W;
    const double w[NB] = {
        C10 * K00,
        C20 * K00,
        C21 * A11, C21 * K10, C21 * A11,
        C30 * K00,
        C31 * A11, C31 * K10, C31 * A11,
        C32 * A22, C32 * A21, C32 * K20, C32 * A21, C32 * A22,
        C40 * K00,
        C41 * A11, C41 * K10, C41 * A11,
        C42 * A22, C42 * A21, C42 * K20, C42 * A21, C42 * A22,
        C43 * A33, C43 * A32, C43 * A31, C43 * K30,
        C43 * A31, C43 * A32, C43 * A33
    };
    for (int i = 0; i < NB; ++i) W.w[i] = (float)w[i];

    static int smem_set = 0;
    if (!smem_set) {
        cudaFuncSetAttribute(dcconv_hmma,
                             cudaFuncAttributeMaxDynamicSharedMemorySize, SM_TOT);
        smem_set = 1;
    }
    // 2 channel halves x 1728 point tiles of 64
    dcconv_hmma<<<2 * (NPTS / 64), THREADS, SM_TOT>>>(pos, coef, (float*)d_out, W);
    (void)out_size;
}

// round 14
// speedup vs baseline: 1.1858x; 1.1858x over previous
#include <cuda_runtime.h>
#include <math.h>
#include <stdint.h>

// R14: split-TF32 HMMA with amortized staging. Block = 256 thr, 128pts x
// 128ch tile, loops NITER=4 point tiles; B staged ONCE per block. Warp =
// 16 pts x 128 ch (16 m16n8 ntiles), B packed {h0,h4,l0,l4} -> 1 LDS.128
// feeds 3 HMMA (hh, hl, lh split product; ll dropped, ~4e-7 rel err).

#define NPTS    110592
#define NB      30
#define KP      32
#define NOI     256
#define THREADS 256
#define PTILE   128
#define NITER   4

// dynamic smem offsets
#define A_HI   0                      // [128][33] f32 = 16896
#define A_LO   16896
#define B_PK   33792                  // [128 ch][272 B]
#define SM_TOT (B_PK + 128 * 272)     // 68608

struct WParams { float w[NB]; };

__device__ __forceinline__ uint32_t f2tf32(float v) {
    uint32_t h; asm("cvt.rna.tf32.f32 %0, %1;" : "=r"(h) : "f"(v)); return h;
}

#define MMA_TF32(ac, a, b0, b1) \
    asm volatile("mma.sync.aligned.m16n8k8.row.col.f32.tf32.tf32.f32 " \
                 "{%0,%1,%2,%3}, {%4,%5,%6,%7}, {%8,%9}, {%0,%1,%2,%3};" \
                 : "+f"((ac)[0]), "+f"((ac)[1]), "+f"((ac)[2]), "+f"((ac)[3]) \
                 : "r"((a)[0]), "r"((a)[1]), "r"((a)[2]), "r"((a)[3]), \
                   "r"(b0), "r"(b1))

__device__ __forceinline__ void basis_eval(float r, float th, float ph,
                                           const float* __restrict__ w,
                                           float* __restrict__ bas)
{
    const float ct  = cosf(th);
    const float st2 = fmaxf(1.0f - ct * ct, 0.0f);
    const float st  = sqrtf(st2);
    const float cp  = cosf(ph);
    const float sp  = sinf(ph);
    const float c2p = cp * cp - sp * sp;
    const float s2p = 2.0f * sp * cp;
    const float c3p = c2p * cp - s2p * sp;
    const float s3p = s2p * cp + c2p * sp;

    const float er1 = expf(-r);
    const float er2 = expf(-0.5f * r);
    const float er3 = expf(-0.33333333333333333f * r);
    const float er4 = expf(-0.25f * r);
    const float rho3 = 0.66666666666666666f * r;
    const float rho4 = 0.5f * r;

    const float F10 = er1;
    const float F20 = er2 * (2.0f - r);
    const float F21 = er2 * r;
    const float F30 = er3 * (3.0f + rho3 * (-3.0f + 0.5f * rho3));
    const float F31 = er3 * rho3 * (4.0f - rho3);
    const float F32 = er3 * rho3 * rho3;
    const float F40 = er4 * (4.0f + rho4 * (-6.0f + rho4 * (2.0f - 0.16666666666666666f * rho4)));
    const float F41 = er4 * rho4 * (10.0f + rho4 * (-5.0f + 0.5f * rho4));
    const float F42 = er4 * rho4 * rho4 * (6.0f - rho4);
    const float F43 = er4 * rho4 * rho4 * rho4;

    const float p10 = ct;
    const float p11 = -st;
    const float p20 = 1.5f * ct * ct - 0.5f;
    const float p21 = -3.0f * ct * st;
    const float p22 = 3.0f * st2;
    const float p30 = (2.5f * ct * ct - 1.5f) * ct;
    const float p31 = (1.5f - 7.5f * ct * ct) * st;
    const float p32 = 15.0f * ct * st2;
    const float p33 = -15.0f * st * st2;

    bas[0]  = w[0]  * F10;
    bas[1]  = w[1]  * F20;
    bas[2]  = w[2]  * F21 * p11 * sp;
    bas[3]  = w[3]  * F21 * p10;
    bas[4]  = w[4]  * F21 * p11 * cp;
    bas[5]  = w[5]  * F30;
    bas[6]  = w[6]  * F31 * p11 * sp;
    bas[7]  = w[7]  * F31 * p10;
    bas[8]  = w[8]  * F31 * p11 * cp;
    bas[9]  = w[9]  * F32 * p22 * s2p;
    bas[10] = w[10] * F32 * p21 * sp;
    bas[11] = w[11] * F32 * p20;
    bas[12] = w[12] * F32 * p21 * cp;
    bas[13] = w[13] * F32 * p22 * c2p;
    bas[14] = w[14] * F40;
    bas[15] = w[15] * F41 * p11 * sp;
    bas[16] = w[16] * F41 * p10;
    bas[17] = w[17] * F41 * p11 * cp;
    bas[18] = w[18] * F42 * p22 * s2p;
    bas[19] = w[19] * F42 * p21 * sp;
    bas[20] = w[20] * F42 * p20;
    bas[21] = w[21] * F42 * p21 * cp;
    bas[22] = w[22] * F42 * p22 * c2p;
    bas[23] = w[23] * F43 * p33 * s3p;
    bas[24] = w[24] * F43 * p32 * s2p;
    bas[25] = w[25] * F43 * p31 * sp;
    bas[26] = w[26] * F43 * p30;
    bas[27] = w[27] * F43 * p31 * cp;
    bas[28] = w[28] * F43 * p32 * c2p;
    bas[29] = w[29] * F43 * p33 * c3p;
}

__global__ __launch_bounds__(THREADS, 2)
void dcconv_hmma2(const float* __restrict__ pos,
                  const float* __restrict__ coef,
                  float* __restrict__ out,
                  WParams W)
{
    extern __shared__ char sm[];
    float* Ahi = (float*)(sm + A_HI);               // [128][33]
    float* Alo = (float*)(sm + A_LO);               // [128][33]
    char*  Bpk = sm + B_PK;                         // [128 ch][272 B]

    const int tid   = threadIdx.x;
    const int lane  = tid & 31;
    const int wid   = tid >> 5;                     // 0..7
    const int half  = blockIdx.x & 1;
    const int group = blockIdx.x >> 1;
    const int ch0   = half * 128;

    // ---- stage B ONCE: thread t<128 packs channel t ----
    if (tid < 128) {
        const float* crow = coef + (size_t)(ch0 + tid) * NB;
#pragma unroll
        for (int ks = 0; ks < 4; ++ks) {
#pragma unroll
            for (int pq = 0; pq < 4; ++pq) {
                const int k = ks * 8 + pq;
                const float v0 = (k     < NB) ? crow[k]     : 0.0f;
                const float v4 = (k + 4 < NB) ? crow[k + 4] : 0.0f;
                const uint32_t h0 = f2tf32(v0);
                const uint32_t h4 = f2tf32(v4);
                const uint32_t l0 = f2tf32(v0 - __uint_as_float(h0));
                const uint32_t l4 = f2tf32(v4 - __uint_as_float(h4));
                *(uint4*)(Bpk + tid * 272 + ks * 64 + pq * 16) =
                    make_uint4(h0, h4, l0, l4);
            }
        }
    }

    const int r = lane >> 2;          // 0..7
    const int q = lane & 3;           // 0..3
    const char* bbase = Bpk + r * 272 + q * 16;

    __syncthreads();

#pragma unroll 1
    for (int it = 0; it < NITER; ++it) {
        const int p0 = (group * NITER + it) * PTILE;

        // ---- stage A: threads 0..127 compute one point's basis ----
        if (tid < 128) {
            const int p = p0 + tid;
            float bas[KP];
            basis_eval(pos[3 * p + 0], pos[3 * p + 1], pos[3 * p + 2], W.w, bas);
            bas[30] = 0.0f; bas[31] = 0.0f;
#pragma unroll
            for (int k = 0; k < KP; ++k) {
                const float v  = bas[k];
                const uint32_t h = f2tf32(v);
                Ahi[tid * 33 + k] = __uint_as_float(h);
                Alo[tid * 33 + k] = __uint_as_float(f2tf32(v - __uint_as_float(h)));
            }
        }
        __syncthreads();

        // ---- A fragments (warp covers 16 pts starting at wid*16) ----
        uint32_t ah[4][4], al[4][4];
        {
            const int row0 = wid * 16 + r;
#pragma unroll
            for (int ks = 0; ks < 4; ++ks) {
                const int kb = ks * 8 + q;
                ah[ks][0] = __float_as_uint(Ahi[row0 * 33 + kb]);
                ah[ks][1] = __float_as_uint(Ahi[(row0 + 8) * 33 + kb]);
                ah[ks][2] = __float_as_uint(Ahi[row0 * 33 + kb + 4]);
                ah[ks][3] = __float_as_uint(Ahi[(row0 + 8) * 33 + kb + 4]);
                al[ks][0] = __float_as_uint(Alo[row0 * 33 + kb]);
                al[ks][1] = __float_as_uint(Alo[(row0 + 8) * 33 + kb]);
                al[ks][2] = __float_as_uint(Alo[row0 * 33 + kb + 4]);
                al[ks][3] = __float_as_uint(Alo[(row0 + 8) * 33 + kb + 4]);
            }
        }

        // ---- mainloop: 16 ntiles x 4 ksteps x 3 HMMA ----
        float acc[16][4];
#pragma unroll
        for (int nt = 0; nt < 16; ++nt) {
            acc[nt][0] = 0.0f; acc[nt][1] = 0.0f;
            acc[nt][2] = 0.0f; acc[nt][3] = 0.0f;
        }
#pragma unroll
        for (int nt = 0; nt < 16; ++nt) {
#pragma unroll
            for (int ks = 0; ks < 4; ++ks) {
                const uint4 bb = *(const uint4*)(bbase + nt * 2176 + ks * 64);
                MMA_TF32(acc[nt], ah[ks], bb.x, bb.y);   // hi x hi
                MMA_TF32(acc[nt], ah[ks], bb.z, bb.w);   // hi x lo
                MMA_TF32(acc[nt], al[ks], bb.x, bb.y);   // lo x hi
            }
        }

        // ---- epilogue: direct frag stores ----
        const int ptA = p0 + wid * 16 + r;
#pragma unroll
        for (int nt = 0; nt < 16; ++nt) {
            const size_t chA = (size_t)(ch0 + nt * 8 + 2 * q);
            out[chA * NPTS + ptA]           = acc[nt][0];
            out[(chA + 1) * NPTS + ptA]     = acc[nt][1];
            out[chA * NPTS + ptA + 8]       = acc[nt][2];
            out[(chA + 1) * NPTS + ptA + 8] = acc[nt][3];
        }
        __syncthreads();   // A reused next iteration
    }
}

extern "C" void kernel_launch(void* const* d_in, const int* in_sizes, int n_in,
                              void* d_out, int out_size)
{
    const float* pos  = (const float*)d_in[0];
    const float* coef = (const float*)d_in[1];
    if (n_in >= 2 && in_sizes[0] == NOI * NB) {
        coef = (const float*)d_in[0];
        pos  = (const float*)d_in[1];
    }

    const double PI  = 3.14159265358979323846;
    const double K00 = sqrt(1.0 / (4.0 * PI));
    const double K10 = sqrt(3.0 / (4.0 * PI));
    const double K20 = sqrt(5.0 / (4.0 * PI));
    const double K30 = sqrt(7.0 / (4.0 * PI));
    const double A11 = sqrt(3.0 / (4.0 * PI));
    const double A21 = sqrt(5.0 / (12.0 * PI));
    const double A22 = sqrt(5.0 / (48.0 * PI));
    const double A31 = sqrt(7.0 / (24.0 * PI));
    const double A32 = sqrt(7.0 / (240.0 * PI));
    const double A33 = sqrt(7.0 / (1440.0 * PI));

    const double C10 = 2.0;
    const double C20 = sqrt(1.0 / 8.0);
    const double C21 = sqrt(1.0 / 24.0);
    const double C30 = sqrt(16.0 / 972.0);
    const double C31 = sqrt(8.0 / 3888.0);
    const double C32 = sqrt(8.0 / 19440.0);
    const double C40 = sqrt(6.0 / 1536.0);
    const double C41 = sqrt(2.0 / 7680.0);
    const double C42 = sqrt(1.0 / 46080.0);
    const double C43 = sqrt(1.0 / 322560.0);

    WParams W;
    const double w[NB] = {
        C10 * K00,
        C20 * K00,
        C21 * A11, C21 * K10, C21 * A11,
        C30 * K00,
        C31 * A11, C31 * K10, C31 * A11,
        C32 * A22, C32 * A21, C32 * K20, C32 * A21, C32 * A22,
        C40 * K00,
        C41 * A11, C41 * K10, C41 * A11,
        C42 * A22, C42 * A21, C42 * K20, C42 * A21, C42 * A22,
        C43 * A33, C43 * A32, C43 * A31, C43 * K30,
        C43 * A31, C43 * A32, C43 * A33
    };
    for (int i = 0; i < NB; ++i) W.w[i] = (float)w[i];

    static int smem_set = 0;
    if (!smem_set) {
        cudaFuncSetAttribute(dcconv_hmma2,
                             cudaFuncAttributeMaxDynamicSharedMemorySize, SM_TOT);
        smem_set = 1;
    }
    // 2 channel halves x (864/NITER) point groups = 432 blocks
    dcconv_hmma2<<<2 * (NPTS / PTILE / NITER), THREADS, SM_TOT>>>(pos, coef, (float*)d_out, W);
    (void)out_size;
}

// round 15
// speedup vs baseline: 1.3571x; 1.1445x over previous
#include <cuda_runtime.h>
#include <math.h>
#include <stdint.h>

// R15: split-TF32 HMMA, warp tile 32pts x 64ch (2 m16 x 8 n8 tiles).
// One B LDS.128 feeds 6 HMMA (2 Mtiles x {hh,hl,lh}), halving B smem
// traffic per output vs R14. Block = 128 thr = 4 warps stacked in points
// (128 pts x 64 ch quarter), NITER=4 point tiles per block, grid 864.

#define NPTS    110592
#define NB      30
#define KP      32
#define NOI     256
#define THREADS 128
#define PTILE   128
#define NITER   4

// dynamic smem offsets
#define A_HI   0                      // [128][33] f32 = 16896
#define A_LO   16896
#define B_PK   33792                  // [64 ch][272 B] = 17408
#define SM_TOT (B_PK + 64 * 272)      // 51200

struct WParams { float w[NB]; };

__device__ __forceinline__ uint32_t f2tf32(float v) {
    uint32_t h; asm("cvt.rna.tf32.f32 %0, %1;" : "=r"(h) : "f"(v)); return h;
}

#define MMA_TF32(ac, a, b0, b1) \
    asm volatile("mma.sync.aligned.m16n8k8.row.col.f32.tf32.tf32.f32 " \
                 "{%0,%1,%2,%3}, {%4,%5,%6,%7}, {%8,%9}, {%0,%1,%2,%3};" \
                 : "+f"((ac)[0]), "+f"((ac)[1]), "+f"((ac)[2]), "+f"((ac)[3]) \
                 : "r"((a)[0]), "r"((a)[1]), "r"((a)[2]), "r"((a)[3]), \
                   "r"(b0), "r"(b1))

__device__ __forceinline__ void basis_eval(float r, float th, float ph,
                                           const float* __restrict__ w,
                                           float* __restrict__ bas)
{
    const float ct  = cosf(th);
    const float st2 = fmaxf(1.0f - ct * ct, 0.0f);
    const float st  = sqrtf(st2);
    const float cp  = cosf(ph);
    const float sp  = sinf(ph);
    const float c2p = cp * cp - sp * sp;
    const float s2p = 2.0f * sp * cp;
    const float c3p = c2p * cp - s2p * sp;
    const float s3p = s2p * cp + c2p * sp;

    const float er1 = expf(-r);
    const float er2 = expf(-0.5f * r);
    const float er3 = expf(-0.33333333333333333f * r);
    const float er4 = expf(-0.25f * r);
    const float rho3 = 0.66666666666666666f * r;
    const float rho4 = 0.5f * r;

    const float F10 = er1;
    const float F20 = er2 * (2.0f - r);
    const float F21 = er2 * r;
    const float F30 = er3 * (3.0f + rho3 * (-3.0f + 0.5f * rho3));
    const float F31 = er3 * rho3 * (4.0f - rho3);
    const float F32 = er3 * rho3 * rho3;
    const float F40 = er4 * (4.0f + rho4 * (-6.0f + rho4 * (2.0f - 0.16666666666666666f * rho4)));
    const float F41 = er4 * rho4 * (10.0f + rho4 * (-5.0f + 0.5f * rho4));
    const float F42 = er4 * rho4 * rho4 * (6.0f - rho4);
    const float F43 = er4 * rho4 * rho4 * rho4;

    const float p10 = ct;
    const float p11 = -st;
    const float p20 = 1.5f * ct * ct - 0.5f;
    const float p21 = -3.0f * ct * st;
    const float p22 = 3.0f * st2;
    const float p30 = (2.5f * ct * ct - 1.5f) * ct;
    const float p31 = (1.5f - 7.5f * ct * ct) * st;
    const float p32 = 15.0f * ct * st2;
    const float p33 = -15.0f * st * st2;

    bas[0]  = w[0]  * F10;
    bas[1]  = w[1]  * F20;
    bas[2]  = w[2]  * F21 * p11 * sp;
    bas[3]  = w[3]  * F21 * p10;
    bas[4]  = w[4]  * F21 * p11 * cp;
    bas[5]  = w[5]  * F30;
    bas[6]  = w[6]  * F31 * p11 * sp;
    bas[7]  = w[7]  * F31 * p10;
    bas[8]  = w[8]  * F31 * p11 * cp;
    bas[9]  = w[9]  * F32 * p22 * s2p;
    bas[10] = w[10] * F32 * p21 * sp;
    bas[11] = w[11] * F32 * p20;
    bas[12] = w[12] * F32 * p21 * cp;
    bas[13] = w[13] * F32 * p22 * c2p;
    bas[14] = w[14] * F40;
    bas[15] = w[15] * F41 * p11 * sp;
    bas[16] = w[16] * F41 * p10;
    bas[17] = w[17] * F41 * p11 * cp;
    bas[18] = w[18] * F42 * p22 * s2p;
    bas[19] = w[19] * F42 * p21 * sp;
    bas[20] = w[20] * F42 * p20;
    bas[21] = w[21] * F42 * p21 * cp;
    bas[22] = w[22] * F42 * p22 * c2p;
    bas[23] = w[23] * F43 * p33 * s3p;
    bas[24] = w[24] * F43 * p32 * s2p;
    bas[25] = w[25] * F43 * p31 * sp;
    bas[26] = w[26] * F43 * p30;
    bas[27] = w[27] * F43 * p31 * cp;
    bas[28] = w[28] * F43 * p32 * c2p;
    bas[29] = w[29] * F43 * p33 * c3p;
}

__global__ __launch_bounds__(THREADS, 3)
void dcconv_hmma3(const float* __restrict__ pos,
                  const float* __restrict__ coef,
                  float* __restrict__ out,
                  WParams W)
{
    extern __shared__ char sm[];
    float* Ahi = (float*)(sm + A_HI);               // [128][33]
    float* Alo = (float*)(sm + A_LO);               // [128][33]
    char*  Bpk = sm + B_PK;                         // [64 ch][272 B]

    const int tid     = threadIdx.x;
    const int lane    = tid & 31;
    const int wid     = tid >> 5;                   // 0..3 (point stacking)
    const int quarter = blockIdx.x & 3;
    const int group   = blockIdx.x >> 2;
    const int ch0     = quarter * 64;

    // ---- stage B ONCE: thread t<128 packs half a channel (2 ksteps) ----
    {
        const int ch = tid >> 1;
        const int h  = tid & 1;
        const float* crow = coef + (size_t)(ch0 + ch) * NB;
#pragma unroll
        for (int ks = 2 * h; ks < 2 * h + 2; ++ks) {
#pragma unroll
            for (int pq = 0; pq < 4; ++pq) {
                const int k = ks * 8 + pq;
                const float v0 = (k     < NB) ? crow[k]     : 0.0f;
                const float v4 = (k + 4 < NB) ? crow[k + 4] : 0.0f;
                const uint32_t h0 = f2tf32(v0);
                const uint32_t h4 = f2tf32(v4);
                const uint32_t l0 = f2tf32(v0 - __uint_as_float(h0));
                const uint32_t l4 = f2tf32(v4 - __uint_as_float(h4));
                *(uint4*)(Bpk + ch * 272 + ks * 64 + pq * 16) =
                    make_uint4(h0, h4, l0, l4);
            }
        }
    }

    const int r = lane >> 2;          // 0..7
    const int q = lane & 3;           // 0..3
    const char* bq = Bpk + r * 272 + q * 16;

#pragma unroll 1
    for (int it = 0; it < NITER; ++it) {
        const int p0 = (group * NITER + it) * PTILE;

        if (it > 0) __syncthreads();   // protect A reuse (B is read-only)

        // ---- stage A: each of 128 threads computes one point's basis ----
        {
            const int p = p0 + tid;
            float bas[KP];
            basis_eval(pos[3 * p + 0], pos[3 * p + 1], pos[3 * p + 2], W.w, bas);
            bas[30] = 0.0f; bas[31] = 0.0f;
#pragma unroll
            for (int k = 0; k < KP; ++k) {
                const float v  = bas[k];
                const uint32_t h = f2tf32(v);
                Ahi[tid * 33 + k] = __uint_as_float(h);
                Alo[tid * 33 + k] = __uint_as_float(f2tf32(v - __uint_as_float(h)));
            }
        }
        __syncthreads();

        // ---- mainloop: ks outer; per B LDS.128 -> 6 HMMA (2 Mtiles) ----
        float acc[2][8][4];
#pragma unroll
        for (int mt = 0; mt < 2; ++mt)
#pragma unroll
            for (int nt = 0; nt < 8; ++nt) {
                acc[mt][nt][0] = 0.0f; acc[mt][nt][1] = 0.0f;
                acc[mt][nt][2] = 0.0f; acc[mt][nt][3] = 0.0f;
            }

#pragma unroll
        for (int ks = 0; ks < 4; ++ks) {
            uint32_t ah[2][4], al[2][4];
            const int kb = ks * 8 + q;
#pragma unroll
            for (int mt = 0; mt < 2; ++mt) {
                const int row0 = wid * 32 + mt * 16 + r;
                ah[mt][0] = __float_as_uint(Ahi[row0 * 33 + kb]);
                ah[mt][1] = __float_as_uint(Ahi[(row0 + 8) * 33 + kb]);
                ah[mt][2] = __float_as_uint(Ahi[row0 * 33 + kb + 4]);
                ah[mt][3] = __float_as_uint(Ahi[(row0 + 8) * 33 + kb + 4]);
                al[mt][0] = __float_as_uint(Alo[row0 * 33 + kb]);
                al[mt][1] = __float_as_uint(Alo[(row0 + 8) * 33 + kb]);
                al[mt][2] = __float_as_uint(Alo[row0 * 33 + kb + 4]);
                al[mt][3] = __float_as_uint(Alo[(row0 + 8) * 33 + kb + 4]);
            }
            const char* bk = bq + ks * 64;
#pragma unroll
            for (int nt = 0; nt < 8; ++nt) {
                const uint4 bb = *(const uint4*)(bk + nt * 2176);
                MMA_TF32(acc[0][nt], ah[0], bb.x, bb.y);   // hi x hi
                MMA_TF32(acc[0][nt], ah[0], bb.z, bb.w);   // hi x lo
                MMA_TF32(acc[0][nt], al[0], bb.x, bb.y);   // lo x hi
                MMA_TF32(acc[1][nt], ah[1], bb.x, bb.y);
                MMA_TF32(acc[1][nt], ah[1], bb.z, bb.w);
                MMA_TF32(acc[1][nt], al[1], bb.x, bb.y);
            }
        }

        // ---- epilogue: direct frag stores (32B sectors, DRAM-dense) ----
#pragma unroll
        for (int mt = 0; mt < 2; ++mt) {
            const int ptA = p0 + wid * 32 + mt * 16 + r;
#pragma unroll
            for (int nt = 0; nt < 8; ++nt) {
                const size_t chA = (size_t)(ch0 + nt * 8 + 2 * q);
                out[chA * NPTS + ptA]           = acc[mt][nt][0];
                out[(chA + 1) * NPTS + ptA]     = acc[mt][nt][1];
                out[chA * NPTS + ptA + 8]       = acc[mt][nt][2];
                out[(chA + 1) * NPTS + ptA + 8] = acc[mt][nt][3];
            }
        }
    }
}

extern "C" void kernel_launch(void* const* d_in, const int* in_sizes, int n_in,
                              void* d_out, int out_size)
{
    const float* pos  = (const float*)d_in[0];
    const float* coef = (const float*)d_in[1];
    if (n_in >= 2 && in_sizes[0] == NOI * NB) {
        coef = (const float*)d_in[0];
        pos  = (const float*)d_in[1];
    }

    const double PI  = 3.14159265358979323846;
    const double K00 = sqrt(1.0 / (4.0 * PI));
    const double K10 = sqrt(3.0 / (4.0 * PI));
    const double K20 = sqrt(5.0 / (4.0 * PI));
    const double K30 = sqrt(7.0 / (4.0 * PI));
    const double A11 = sqrt(3.0 / (4.0 * PI));
    const double A21 = sqrt(5.0 / (12.0 * PI));
    const double A22 = sqrt(5.0 / (48.0 * PI));
    const double A31 = sqrt(7.0 / (24.0 * PI));
    const double A32 = sqrt(7.0 / (240.0 * PI));
    const double A33 = sqrt(7.0 / (1440.0 * PI));

    const double C10 = 2.0;
    const double C20 = sqrt(1.0 / 8.0);
    const double C21 = sqrt(1.0 / 24.0);
    const double C30 = sqrt(16.0 / 972.0);
    const double C31 = sqrt(8.0 / 3888.0);
    const double C32 = sqrt(8.0 / 19440.0);
    const double C40 = sqrt(6.0 / 1536.0);
    const double C41 = sqrt(2.0 / 7680.0);
    const double C42 = sqrt(1.0 / 46080.0);
    const double C43 = sqrt(1.0 / 322560.0);

    WParams W;
    const double w[NB] = {
        C10 * K00,
        C20 * K00,
        C21 * A11, C21 * K10, C21 * A11,
        C30 * K00,
        C31 * A11, C31 * K10, C31 * A11,
        C32 * A22, C32 * A21, C32 * K20, C32 * A21, C32 * A22,
        C40 * K00,
        C41 * A11, C41 * K10, C41 * A11,
        C42 * A22, C42 * A21, C42 * K20, C42 * A21, C42 * A22,
        C43 * A33, C43 * A32, C43 * A31, C43 * K30,
        C43 * A31, C43 * A32, C43 * A33
    };
    for (int i = 0; i < NB; ++i) W.w[i] = (float)w[i];

    static int smem_set = 0;
    if (!smem_set) {
        cudaFuncSetAttribute(dcconv_hmma3,
                             cudaFuncAttributeMaxDynamicSharedMemorySize, SM_TOT);
        smem_set = 1;
    }
    // 4 channel quarters x 216 point groups = 864 blocks
    dcconv_hmma3<<<4 * (NPTS / PTILE / NITER), THREADS, SM_TOT>>>(pos, coef, (float*)d_out, W);
    (void)out_size;
}

// round 17
// speedup vs baseline: 1.5731x; 1.1591x over previous
#include <cuda_runtime.h>
#include <math.h>
#include <stdint.h>

// R17: resubmit of R16 (infra failure, no kernel signal).
// R15 + A smem row stride 33 -> 36 floats. A-frag LDS bank pattern
// becomes (4r + q) mod 32: conflict-free (was 4-way at stride 33).
// Warp tile 32pts x 64ch, 1 B LDS.128 -> 6 HMMA, NITER=4, grid 864.

#define NPTS    110592
#define NB      30
#define KP      32
#define NOI     256
#define THREADS 128
#define PTILE   128
#define NITER   4
#define ASTR    36                    // A row stride in floats (conflict-free)

// dynamic smem offsets
#define A_HI   0                      // [128][36] f32 = 18432
#define A_LO   18432
#define B_PK   36864                  // [64 ch][272 B] = 17408
#define SM_TOT (B_PK + 64 * 272)      // 54272

struct WParams { float w[NB]; };

__device__ __forceinline__ uint32_t f2tf32(float v) {
    uint32_t h; asm("cvt.rna.tf32.f32 %0, %1;" : "=r"(h) : "f"(v)); return h;
}

#define MMA_TF32(ac, a, b0, b1) \
    asm volatile("mma.sync.aligned.m16n8k8.row.col.f32.tf32.tf32.f32 " \
                 "{%0,%1,%2,%3}, {%4,%5,%6,%7}, {%8,%9}, {%0,%1,%2,%3};" \
                 : "+f"((ac)[0]), "+f"((ac)[1]), "+f"((ac)[2]), "+f"((ac)[3]) \
                 : "r"((a)[0]), "r"((a)[1]), "r"((a)[2]), "r"((a)[3]), \
                   "r"(b0), "r"(b1))

__device__ __forceinline__ void basis_eval(float r, float th, float ph,
                                           const float* __restrict__ w,
                                           float* __restrict__ bas)
{
    const float ct  = cosf(th);
    const float st2 = fmaxf(1.0f - ct * ct, 0.0f);
    const float st  = sqrtf(st2);
    const float cp  = cosf(ph);
    const float sp  = sinf(ph);
    const float c2p = cp * cp - sp * sp;
    const float s2p = 2.0f * sp * cp;
    const float c3p = c2p * cp - s2p * sp;
    const float s3p = s2p * cp + c2p * sp;

    const float er1 = expf(-r);
    const float er2 = expf(-0.5f * r);
    const float er3 = expf(-0.33333333333333333f * r);
    const float er4 = expf(-0.25f * r);
    const float rho3 = 0.66666666666666666f * r;
    const float rho4 = 0.5f * r;

    const float F10 = er1;
    const float F20 = er2 * (2.0f - r);
    const float F21 = er2 * r;
    const float F30 = er3 * (3.0f + rho3 * (-3.0f + 0.5f * rho3));
    const float F31 = er3 * rho3 * (4.0f - rho3);
    const float F32 = er3 * rho3 * rho3;
    const float F40 = er4 * (4.0f + rho4 * (-6.0f + rho4 * (2.0f - 0.16666666666666666f * rho4)));
    const float F41 = er4 * rho4 * (10.0f + rho4 * (-5.0f + 0.5f * rho4));
    const float F42 = er4 * rho4 * rho4 * (6.0f - rho4);
    const float F43 = er4 * rho4 * rho4 * rho4;

    const float p10 = ct;
    const float p11 = -st;
    const float p20 = 1.5f * ct * ct - 0.5f;
    const float p21 = -3.0f * ct * st;
    const float p22 = 3.0f * st2;
    const float p30 = (2.5f * ct * ct - 1.5f) * ct;
    const float p31 = (1.5f - 7.5f * ct * ct) * st;
    const float p32 = 15.0f * ct * st2;
    const float p33 = -15.0f * st * st2;

    bas[0]  = w[0]  * F10;
    bas[1]  = w[1]  * F20;
    bas[2]  = w[2]  * F21 * p11 * sp;
    bas[3]  = w[3]  * F21 * p10;
    bas[4]  = w[4]  * F21 * p11 * cp;
    bas[5]  = w[5]  * F30;
    bas[6]  = w[6]  * F31 * p11 * sp;
    bas[7]  = w[7]  * F31 * p10;
    bas[8]  = w[8]  * F31 * p11 * cp;
    bas[9]  = w[9]  * F32 * p22 * s2p;
    bas[10] = w[10] * F32 * p21 * sp;
    bas[11] = w[11] * F32 * p20;
    bas[12] = w[12] * F32 * p21 * cp;
    bas[13] = w[13] * F32 * p22 * c2p;
    bas[14] = w[14] * F40;
    bas[15] = w[15] * F41 * p11 * sp;
    bas[16] = w[16] * F41 * p10;
    bas[17] = w[17] * F41 * p11 * cp;
    bas[18] = w[18] * F42 * p22 * s2p;
    bas[19] = w[19] * F42 * p21 * sp;
    bas[20] = w[20] * F42 * p20;
    bas[21] = w[21] * F42 * p21 * cp;
    bas[22] = w[22] * F42 * p22 * c2p;
    bas[23] = w[23] * F43 * p33 * s3p;
    bas[24] = w[24] * F43 * p32 * s2p;
    bas[25] = w[25] * F43 * p31 * sp;
    bas[26] = w[26] * F43 * p30;
    bas[27] = w[27] * F43 * p31 * cp;
    bas[28] = w[28] * F43 * p32 * c2p;
    bas[29] = w[29] * F43 * p33 * c3p;
}

__global__ __launch_bounds__(THREADS, 3)
void dcconv_hmma4(const float* __restrict__ pos,
                  const float* __restrict__ coef,
                  float* __restrict__ out,
                  WParams W)
{
    extern __shared__ char sm[];
    float* Ahi = (float*)(sm + A_HI);               // [128][ASTR]
    float* Alo = (float*)(sm + A_LO);               // [128][ASTR]
    char*  Bpk = sm + B_PK;                         // [64 ch][272 B]

    const int tid     = threadIdx.x;
    const int lane    = tid & 31;
    const int wid     = tid >> 5;                   // 0..3 (point stacking)
    const int quarter = blockIdx.x & 3;
    const int group   = blockIdx.x >> 2;
    const int ch0     = quarter * 64;

    // ---- stage B ONCE: thread t<128 packs half a channel (2 ksteps) ----
    {
        const int ch = tid >> 1;
        const int h  = tid & 1;
        const float* crow = coef + (size_t)(ch0 + ch) * NB;
#pragma unroll
        for (int ks = 2 * h; ks < 2 * h + 2; ++ks) {
#pragma unroll
            for (int pq = 0; pq < 4; ++pq) {
                const int k = ks * 8 + pq;
                const float v0 = (k     < NB) ? crow[k]     : 0.0f;
                const float v4 = (k + 4 < NB) ? crow[k + 4] : 0.0f;
                const uint32_t h0 = f2tf32(v0);
                const uint32_t h4 = f2tf32(v4);
                const uint32_t l0 = f2tf32(v0 - __uint_as_float(h0));
                const uint32_t l4 = f2tf32(v4 - __uint_as_float(h4));
                *(uint4*)(Bpk + ch * 272 + ks * 64 + pq * 16) =
                    make_uint4(h0, h4, l0, l4);
            }
        }
    }

    const int r = lane >> 2;          // 0..7
    const int q = lane & 3;           // 0..3
    const char* bq = Bpk + r * 272 + q * 16;

#pragma unroll 1
    for (int it = 0; it < NITER; ++it) {
        const int p0 = (group * NITER + it) * PTILE;

        if (it > 0) __syncthreads();   // protect A reuse (B is read-only)

        // ---- stage A: each of 128 threads computes one point's basis ----
        {
            const int p = p0 + tid;
            float bas[KP];
            basis_eval(pos[3 * p + 0], pos[3 * p + 1], pos[3 * p + 2], W.w, bas);
            bas[30] = 0.0f; bas[31] = 0.0f;
#pragma unroll
            for (int k = 0; k < KP; ++k) {
                const float v  = bas[k];
                const uint32_t h = f2tf32(v);
                Ahi[tid * ASTR + k] = __uint_as_float(h);
                Alo[tid * ASTR + k] = __uint_as_float(f2tf32(v - __uint_as_float(h)));
            }
        }
        __syncthreads();

        // ---- mainloop: ks outer; per B LDS.128 -> 6 HMMA (2 Mtiles) ----
        float acc[2][8][4];
#pragma unroll
        for (int mt = 0; mt < 2; ++mt)
#pragma unroll
            for (int nt = 0; nt < 8; ++nt) {
                acc[mt][nt][0] = 0.0f; acc[mt][nt][1] = 0.0f;
                acc[mt][nt][2] = 0.0f; acc[mt][nt][3] = 0.0f;
            }

#pragma unroll
        for (int ks = 0; ks < 4; ++ks) {
            uint32_t ah[2][4], al[2][4];
            const int kb = ks * 8 + q;
#pragma unroll
            for (int mt = 0; mt < 2; ++mt) {
                const int row0 = wid * 32 + mt * 16 + r;
                ah[mt][0] = __float_as_uint(Ahi[row0 * ASTR + kb]);
                ah[mt][1] = __float_as_uint(Ahi[(row0 + 8) * ASTR + kb]);
                ah[mt][2] = __float_as_uint(Ahi[row0 * ASTR + kb + 4]);
                ah[mt][3] = __float_as_uint(Ahi[(row0 + 8) * ASTR + kb + 4]);
                al[mt][0] = __float_as_uint(Alo[row0 * ASTR + kb]);
                al[mt][1] = __float_as_uint(Alo[(row0 + 8) * ASTR + kb]);
                al[mt][2] = __float_as_uint(Alo[row0 * ASTR + kb + 4]);
                al[mt][3] = __float_as_uint(Alo[(row0 + 8) * ASTR + kb + 4]);
            }
            const char* bk = bq + ks * 64;
#pragma unroll
            for (int nt = 0; nt < 8; ++nt) {
                const uint4 bb = *(const uint4*)(bk + nt * 2176);
                MMA_TF32(acc[0][nt], ah[0], bb.x, bb.y);   // hi x hi
                MMA_TF32(acc[0][nt], ah[0], bb.z, bb.w);   // hi x lo
                MMA_TF32(acc[0][nt], al[0], bb.x, bb.y);   // lo x hi
                MMA_TF32(acc[1][nt], ah[1], bb.x, bb.y);
                MMA_TF32(acc[1][nt], ah[1], bb.z, bb.w);
                MMA_TF32(acc[1][nt], al[1], bb.x, bb.y);
            }
        }

        // ---- epilogue: direct frag stores (32B sectors, DRAM-dense) ----
#pragma unroll
        for (int mt = 0; mt < 2; ++mt) {
            const int ptA = p0 + wid * 32 + mt * 16 + r;
#pragma unroll
            for (int nt = 0; nt < 8; ++nt) {
                const size_t chA = (size_t)(ch0 + nt * 8 + 2 * q);
                out[chA * NPTS + ptA]           = acc[mt][nt][0];
                out[(chA + 1) * NPTS + ptA]     = acc[mt][nt][1];
                out[chA * NPTS + ptA + 8]       = acc[mt][nt][2];
                out[(chA + 1) * NPTS + ptA + 8] = acc[mt][nt][3];
            }
        }
    }
}

extern "C" void kernel_launch(void* const* d_in, const int* in_sizes, int n_in,
                              void* d_out, int out_size)
{
    const float* pos  = (const float*)d_in[0];
    const float* coef = (const float*)d_in[1];
    if (n_in >= 2 && in_sizes[0] == NOI * NB) {
        coef = (const float*)d_in[0];
        pos  = (const float*)d_in[1];
    }

    const double PI  = 3.14159265358979323846;
    const double K00 = sqrt(1.0 / (4.0 * PI));
    const double K10 = sqrt(3.0 / (4.0 * PI));
    const double K20 = sqrt(5.0 / (4.0 * PI));
    const double K30 = sqrt(7.0 / (4.0 * PI));
    const double A11 = sqrt(3.0 / (4.0 * PI));
    const double A21 = sqrt(5.0 / (12.0 * PI));
    const double A22 = sqrt(5.0 / (48.0 * PI));
    const double A31 = sqrt(7.0 / (24.0 * PI));
    const double A32 = sqrt(7.0 / (240.0 * PI));
    const double A33 = sqrt(7.0 / (1440.0 * PI));

    const double C10 = 2.0;
    const double C20 = sqrt(1.0 / 8.0);
    const double C21 = sqrt(1.0 / 24.0);
    const double C30 = sqrt(16.0 / 972.0);
    const double C31 = sqrt(8.0 / 3888.0);
    const double C32 = sqrt(8.0 / 19440.0);
    const double C40 = sqrt(6.0 / 1536.0);
    const double C41 = sqrt(2.0 / 7680.0);
    const double C42 = sqrt(1.0 / 46080.0);
    const double C43 = sqrt(1.0 / 322560.0);

    WParams W;
    const double w[NB] = {
        C10 * K00,
        C20 * K00,
        C21 * A11, C21 * K10, C21 * A11,
        C30 * K00,
        C31 * A11, C31 * K10, C31 * A11,
        C32 * A22, C32 * A21, C32 * K20, C32 * A21, C32 * A22,
        C40 * K00,
        C41 * A11, C41 * K10, C41 * A11,
        C42 * A22, C42 * A21, C42 * K20, C42 * A21, C42 * A22,
        C43 * A33, C43 * A32, C43 * A31, C43 * K30,
        C43 * A31, C43 * A32, C43 * A33
    };
    for (int i = 0; i < NB; ++i) W.w[i] = (float)w[i];

    static int smem_set = 0;
    if (!smem_set) {
        cudaFuncSetAttribute(dcconv_hmma4,
                             cudaFuncAttributeMaxDynamicSharedMemorySize, SM_TOT);
        smem_set = 1;
    }
    // 4 channel quarters x 216 point groups = 864 blocks
    dcconv_hmma4<<<4 * (NPTS / PTILE / NITER), THREADS, SM_TOT>>>(pos, coef, (float*)d_out, W);
    (void)out_size;
}